// round 10
// baseline (speedup 1.0000x reference)
#include <cuda_runtime.h>
#include <cuda_bf16.h>

// Depthwise conv1d, fixed shape: B=4, D=2048, L=8192, K=3, pad=1 -> L_out=L.
// out[b,d,l] = bias[d] + w[d,0]*x[l-1] + w[d,1]*x[l] + w[d,2]*x[l+1]
//
// Warp-coalesced single-tile kernel: a warp owns 512 contiguous elements
// (4 chunks of 32 float4); lane i handles float4 #i, #i+32, #i+64, #i+96.
// Every LDG.128/STG.128 is a dense 512B warp transaction; per-thread MLP=4.
// One base address + one weight/bias set per warp (512 | 8192 -> warp never
// straddles a row) keeps register count low so occupancy recovers.
// All halos via warp shuffle except the two warp-edge elements.

#define CONV_B 4
#define CONV_D 2048
#define CONV_L 8192
#define TOTAL_ELEMS (CONV_B * CONV_D * CONV_L)      // 67,108,864
#define WARP_ELEMS 512

__global__ __launch_bounds__(256, 6) void dwconv1d_k3_kernel(
    const float* __restrict__ x,     // [B*D, L]
    const float* __restrict__ w,     // [D, 3]
    const float* __restrict__ bias,  // [D]
    float* __restrict__ out)         // [B*D, L]
{
    const unsigned tid    = blockIdx.x * blockDim.x + threadIdx.x;
    const unsigned lane   = threadIdx.x & 31;
    const unsigned Wb     = (tid >> 5) * WARP_ELEMS;   // warp-base element

    // ---- 4 dense front-batched LDG.128 (512B per warp each) ----
    const float4* xv = reinterpret_cast<const float4*>(x + Wb);
    float4 c0 = xv[lane];
    float4 c1 = xv[lane + 32];
    float4 c2 = xv[lane + 64];
    float4 c3 = xv[lane + 96];

    // ---- weights / bias: uniform across warp ----
    const unsigned d = (Wb >> 13) & (CONV_D - 1);
    const float w0 = __ldg(&w[d * 3 + 0]);
    const float w1 = __ldg(&w[d * 3 + 1]);
    const float w2 = __ldg(&w[d * 3 + 2]);
    const float bv = __ldg(&bias[d]);
    const unsigned lpos = Wb & (CONV_L - 1);           // 512-aligned row pos

    // ---- halo exchange via shuffles ----
    // chunk j, lane i: left = lane i-1's cj.w; lane 0 takes lane 31's c(j-1).w
    //                  right = lane i+1's cj.x; lane 31 takes lane 0's c(j+1).x
    // warp edges (chunk0 lane0 left, chunk3 lane31 right) come from memory.
    float l0 = __shfl_up_sync(0xffffffffu, c0.w, 1);
    float l1 = __shfl_up_sync(0xffffffffu, c1.w, 1);
    float l2 = __shfl_up_sync(0xffffffffu, c2.w, 1);
    float l3 = __shfl_up_sync(0xffffffffu, c3.w, 1);
    float r0 = __shfl_down_sync(0xffffffffu, c0.x, 1);
    float r1 = __shfl_down_sync(0xffffffffu, c1.x, 1);
    float r2 = __shfl_down_sync(0xffffffffu, c2.x, 1);
    float r3 = __shfl_down_sync(0xffffffffu, c3.x, 1);

    const float c0w31 = __shfl_sync(0xffffffffu, c0.w, 31);
    const float c1w31 = __shfl_sync(0xffffffffu, c1.w, 31);
    const float c2w31 = __shfl_sync(0xffffffffu, c2.w, 31);
    const float c1x0  = __shfl_sync(0xffffffffu, c1.x, 0);
    const float c2x0  = __shfl_sync(0xffffffffu, c2.x, 0);
    const float c3x0  = __shfl_sync(0xffffffffu, c3.x, 0);

    if (lane == 0) {
        l1 = c0w31;
        l2 = c1w31;
        l3 = c2w31;
        l0 = (lpos > 0) ? __ldg(x + Wb - 1) : 0.0f;
    }
    if (lane == 31) {
        r0 = c1x0;
        r1 = c2x0;
        r2 = c3x0;
        r3 = (lpos + WARP_ELEMS < CONV_L) ? __ldg(x + Wb + WARP_ELEMS) : 0.0f;
    }

    // ---- compute + dense streaming stores ----
    float4* ov = reinterpret_cast<float4*>(out + Wb);

    float4 o;
    o.x = fmaf(w0, l0,   fmaf(w1, c0.x, fmaf(w2, c0.y, bv)));
    o.y = fmaf(w0, c0.x, fmaf(w1, c0.y, fmaf(w2, c0.z, bv)));
    o.z = fmaf(w0, c0.y, fmaf(w1, c0.z, fmaf(w2, c0.w, bv)));
    o.w = fmaf(w0, c0.z, fmaf(w1, c0.w, fmaf(w2, r0,   bv)));
    __stcs(&ov[lane], o);

    o.x = fmaf(w0, l1,   fmaf(w1, c1.x, fmaf(w2, c1.y, bv)));
    o.y = fmaf(w0, c1.x, fmaf(w1, c1.y, fmaf(w2, c1.z, bv)));
    o.z = fmaf(w0, c1.y, fmaf(w1, c1.z, fmaf(w2, c1.w, bv)));
    o.w = fmaf(w0, c1.z, fmaf(w1, c1.w, fmaf(w2, r1,   bv)));
    __stcs(&ov[lane + 32], o);

    o.x = fmaf(w0, l2,   fmaf(w1, c2.x, fmaf(w2, c2.y, bv)));
    o.y = fmaf(w0, c2.x, fmaf(w1, c2.y, fmaf(w2, c2.z, bv)));
    o.z = fmaf(w0, c2.y, fmaf(w1, c2.z, fmaf(w2, c2.w, bv)));
    o.w = fmaf(w0, c2.z, fmaf(w1, c2.w, fmaf(w2, r2,   bv)));
    __stcs(&ov[lane + 64], o);

    o.x = fmaf(w0, l3,   fmaf(w1, c3.x, fmaf(w2, c3.y, bv)));
    o.y = fmaf(w0, c3.x, fmaf(w1, c3.y, fmaf(w2, c3.z, bv)));
    o.z = fmaf(w0, c3.y, fmaf(w1, c3.z, fmaf(w2, c3.w, bv)));
    o.w = fmaf(w0, c3.z, fmaf(w1, c3.w, fmaf(w2, r3,   bv)));
    __stcs(&ov[lane + 96], o);
}

extern "C" void kernel_launch(void* const* d_in, const int* in_sizes, int n_in,
                              void* d_out, int out_size)
{
    const float* x    = (const float*)d_in[0];
    const float* w    = (const float*)d_in[1];
    const float* bias = (const float*)d_in[2];
    float*       out  = (float*)d_out;

    // 8 warps/CTA x 512 elems/warp = 4096 elems/CTA
    const int threads = 256;
    const int blocks  = TOTAL_ELEMS / 4096;    // 16384

    dwconv1d_k3_kernel<<<blocks, threads>>>(x, w, bias, out);
}

// round 11
// speedup vs baseline: 1.0051x; 1.0051x over previous
#include <cuda_runtime.h>
#include <cuda_bf16.h>

// Depthwise conv1d, fixed shape: B=4, D=2048, L=8192, K=3, pad=1 -> L_out=L.
// out[b,d,l] = bias[d] + w[d,0]*x[l-1] + w[d,1]*x[l] + w[d,2]*x[l+1]
//
// Quad-batch-stream warp-coalesced kernel. Key fact: TOTAL/4 = 16,777,216
// elements = exactly D*L, so stream s = batch s with IDENTICAL (d, l).
// A warp owns 128 contiguous elements at the same (d,l) in each of the 4
// batches: 4 dense 512B LDG.128 warp transactions (MLP=4 across 4 distant
// DRAM regions), ONE shared weight/bias set and ONE row-position for all
// streams (saves ~12 regs vs per-stream weights -> occupancy recovers).
// Halos via warp shuffle; only warp-edge lanes touch memory.

#define CONV_B 4
#define CONV_D 2048
#define CONV_L 8192
#define TOTAL_ELEMS (CONV_B * CONV_D * CONV_L)      // 67,108,864
#define BATCH_STRIDE (CONV_D * CONV_L)              // 16,777,216 elems
#define WARP_TILE 128                               // elems per warp per stream

__global__ __launch_bounds__(256, 6) void dwconv1d_k3_kernel(
    const float* __restrict__ x,     // [B, D, L]
    const float* __restrict__ w,     // [D, 3]
    const float* __restrict__ bias,  // [D]
    float* __restrict__ out)         // [B, D, L]
{
    const unsigned tid  = blockIdx.x * blockDim.x + threadIdx.x;
    const unsigned lane = threadIdx.x & 31;
    const unsigned Wb   = (tid >> 5) * WARP_TILE;    // base within batch 0

    // ---- 4 dense front-batched LDG.128 (one per batch-stream) ----
    float4 v0, v1, v2, v3;
    {
        const float4* p0 = reinterpret_cast<const float4*>(x + Wb);
        const float4* p1 = reinterpret_cast<const float4*>(x + Wb + 1u * BATCH_STRIDE);
        const float4* p2 = reinterpret_cast<const float4*>(x + Wb + 2u * BATCH_STRIDE);
        const float4* p3 = reinterpret_cast<const float4*>(x + Wb + 3u * BATCH_STRIDE);
        v0 = p0[lane];
        v1 = p1[lane];
        v2 = p2[lane];
        v3 = p3[lane];
    }

    // ---- shared weights / bias / row position (identical for all streams) ----
    const unsigned d    = (Wb >> 13) & (CONV_D - 1);
    const unsigned lpos = Wb & (CONV_L - 1);
    const float w0 = __ldg(&w[d * 3 + 0]);
    const float w1 = __ldg(&w[d * 3 + 1]);
    const float w2 = __ldg(&w[d * 3 + 2]);
    const float bv = __ldg(&bias[d]);

    // ---- halos via shuffle; warp-edge lanes fall back to memory ----
    float l0 = __shfl_up_sync(0xffffffffu, v0.w, 1);
    float l1 = __shfl_up_sync(0xffffffffu, v1.w, 1);
    float l2 = __shfl_up_sync(0xffffffffu, v2.w, 1);
    float l3 = __shfl_up_sync(0xffffffffu, v3.w, 1);
    float r0 = __shfl_down_sync(0xffffffffu, v0.x, 1);
    float r1 = __shfl_down_sync(0xffffffffu, v1.x, 1);
    float r2 = __shfl_down_sync(0xffffffffu, v2.x, 1);
    float r3 = __shfl_down_sync(0xffffffffu, v3.x, 1);

    if (lane == 0) {
        const bool in = (lpos > 0);
        l0 = in ? __ldg(x + Wb - 1)                    : 0.0f;
        l1 = in ? __ldg(x + Wb + 1u * BATCH_STRIDE - 1) : 0.0f;
        l2 = in ? __ldg(x + Wb + 2u * BATCH_STRIDE - 1) : 0.0f;
        l3 = in ? __ldg(x + Wb + 3u * BATCH_STRIDE - 1) : 0.0f;
    }
    if (lane == 31) {
        const bool in = (lpos + WARP_TILE < CONV_L);
        r0 = in ? __ldg(x + Wb + WARP_TILE)                    : 0.0f;
        r1 = in ? __ldg(x + Wb + 1u * BATCH_STRIDE + WARP_TILE) : 0.0f;
        r2 = in ? __ldg(x + Wb + 2u * BATCH_STRIDE + WARP_TILE) : 0.0f;
        r3 = in ? __ldg(x + Wb + 3u * BATCH_STRIDE + WARP_TILE) : 0.0f;
    }

    // ---- 4 independent compute + dense streaming store chains ----
    float4 o;

    o.x = fmaf(w0, l0,   fmaf(w1, v0.x, fmaf(w2, v0.y, bv)));
    o.y = fmaf(w0, v0.x, fmaf(w1, v0.y, fmaf(w2, v0.z, bv)));
    o.z = fmaf(w0, v0.y, fmaf(w1, v0.z, fmaf(w2, v0.w, bv)));
    o.w = fmaf(w0, v0.z, fmaf(w1, v0.w, fmaf(w2, r0,   bv)));
    __stcs(&reinterpret_cast<float4*>(out + Wb)[lane], o);

    o.x = fmaf(w0, l1,   fmaf(w1, v1.x, fmaf(w2, v1.y, bv)));
    o.y = fmaf(w0, v1.x, fmaf(w1, v1.y, fmaf(w2, v1.z, bv)));
    o.z = fmaf(w0, v1.y, fmaf(w1, v1.z, fmaf(w2, v1.w, bv)));
    o.w = fmaf(w0, v1.z, fmaf(w1, v1.w, fmaf(w2, r1,   bv)));
    __stcs(&reinterpret_cast<float4*>(out + Wb + 1u * BATCH_STRIDE)[lane], o);

    o.x = fmaf(w0, l2,   fmaf(w1, v2.x, fmaf(w2, v2.y, bv)));
    o.y = fmaf(w0, v2.x, fmaf(w1, v2.y, fmaf(w2, v2.z, bv)));
    o.z = fmaf(w0, v2.y, fmaf(w1, v2.z, fmaf(w2, v2.w, bv)));
    o.w = fmaf(w0, v2.z, fmaf(w1, v2.w, fmaf(w2, r2,   bv)));
    __stcs(&reinterpret_cast<float4*>(out + Wb + 2u * BATCH_STRIDE)[lane], o);

    o.x = fmaf(w0, l3,   fmaf(w1, v3.x, fmaf(w2, v3.y, bv)));
    o.y = fmaf(w0, v3.x, fmaf(w1, v3.y, fmaf(w2, v3.z, bv)));
    o.z = fmaf(w0, v3.y, fmaf(w1, v3.z, fmaf(w2, v3.w, bv)));
    o.w = fmaf(w0, v3.z, fmaf(w1, v3.w, fmaf(w2, r3,   bv)));
    __stcs(&reinterpret_cast<float4*>(out + Wb + 3u * BATCH_STRIDE)[lane], o);
}

extern "C" void kernel_launch(void* const* d_in, const int* in_sizes, int n_in,
                              void* d_out, int out_size)
{
    const float* x    = (const float*)d_in[0];
    const float* w    = (const float*)d_in[1];
    const float* bias = (const float*)d_in[2];
    float*       out  = (float*)d_out;

    // each warp: 128 elems x 4 batches = 512 elems; 8 warps/CTA = 4096/CTA
    const int threads = 256;
    const int blocks  = TOTAL_ELEMS / 4096;    // 16384

    dwconv1d_k3_kernel<<<blocks, threads>>>(x, w, bias, out);
}